// round 12
// baseline (speedup 1.0000x reference)
#include <cuda_runtime.h>
#include <cuda_bf16.h>
#include <cstdint>

// Problem constants
#define NA     100000
#define NBND   200000
#define MAXNB  6
#define AF     133
#define BF     147
#define HID    300
#define NM     8192
#define NPAD   320
#define NBP    200192   // NBND rounded up to 256

// Scratch (device globals)
__device__ float g_inp [NBND * HID];
__device__ float g_bufA[NBND * HID];
__device__ float g_bufB[NBND * HID];
__device__ float g_amsg[NA   * HID];
__device__ float g_hid [NA   * HID];

// Shared A-operand bf16 hi/lo buffer (reused: bonds[x160] -> pre[x320] -> cat[x448])
__device__ __align__(16) unsigned short g_Ahi[NBP * 320];
__device__ __align__(16) unsigned short g_Alo[NBP * 320];

// Pre-split transposed weights: Wt[n][k] bf16, zero-padded
__device__ __align__(16) unsigned short g_Wi_hi[NPAD * 160], g_Wi_lo[NPAD * 160];
__device__ __align__(16) unsigned short g_Wh_hi[NPAD * 320], g_Wh_lo[NPAD * 320];
__device__ __align__(16) unsigned short g_Wo_hi[NPAD * 448], g_Wo_lo[NPAD * 448];

#define MMA16816(d, a, b) \
    asm volatile("mma.sync.aligned.m16n8k16.row.col.f32.bf16.bf16.f32 " \
        "{%0,%1,%2,%3}, {%4,%5,%6,%7}, {%8,%9}, {%0,%1,%2,%3};" \
        : "+f"((d)[0]), "+f"((d)[1]), "+f"((d)[2]), "+f"((d)[3]) \
        : "r"((a)[0]), "r"((a)[1]), "r"((a)[2]), "r"((a)[3]), \
          "r"((b)[0]), "r"((b)[1]))

#define LDSM_X4(r0_, r1_, r2_, r3_, addr) \
    asm volatile("ldmatrix.sync.aligned.m8n8.x4.shared.b16 {%0,%1,%2,%3}, [%4];" \
        : "=r"(r0_), "=r"(r1_), "=r"(r2_), "=r"(r3_) : "r"(addr))

#define CP_ASYNC16(dst, src) \
    asm volatile("cp.async.cg.shared.global [%0], [%1], 16;" :: "r"(dst), "l"(src))
#define CP_COMMIT() asm volatile("cp.async.commit_group;")
#define CP_WAIT0()  asm volatile("cp.async.wait_group 0;")
#define CP_WAIT1()  asm volatile("cp.async.wait_group 1;")

__device__ __forceinline__ void split2(float v0, float v1, uint32_t& h, uint32_t& l)
{
    __nv_bfloat16 h0 = __float2bfloat16(v0), h1 = __float2bfloat16(v1);
    __nv_bfloat16 l0 = __float2bfloat16(v0 - __bfloat162float(h0));
    __nv_bfloat16 l1 = __float2bfloat16(v1 - __bfloat162float(h1));
    h = (uint32_t)__bfloat16_as_ushort(h0) | ((uint32_t)__bfloat16_as_ushort(h1) << 16);
    l = (uint32_t)__bfloat16_as_ushort(l0) | ((uint32_t)__bfloat16_as_ushort(l1) << 16);
}

// ---------------------------------------------------------------------------
// Split kernels
// ---------------------------------------------------------------------------
__global__ void wsplit_kernel(const float* __restrict__ W, unsigned short* __restrict__ hi,
                              unsigned short* __restrict__ lo, int K, int Kp)
{
    int idx = blockIdx.x * blockDim.x + threadIdx.x;
    if (idx >= NPAD * Kp) return;
    int n = idx / Kp, k = idx - n * Kp;
    float v = (n < HID && k < K) ? W[k * HID + n] : 0.f;
    __nv_bfloat16 h = __float2bfloat16(v);
    __nv_bfloat16 l = __float2bfloat16(v - __bfloat162float(h));
    hi[idx] = __bfloat16_as_ushort(h);
    lo[idx] = __bfloat16_as_ushort(l);
}

// f_bonds [NBND x 147] -> Ahi/Alo [NBND x 160]
__global__ __launch_bounds__(256)
void bsplit_kernel(const float* __restrict__ f_bonds,
                   unsigned short* __restrict__ Ah, unsigned short* __restrict__ Al)
{
    int idx = blockIdx.x * blockDim.x + threadIdx.x;   // pairs
    if (idx >= NBND * 80) return;
    int b = idx / 80, p = idx - b * 80;
    int k = 2 * p;
    float v0 = (k < BF)     ? f_bonds[b * BF + k]     : 0.f;
    float v1 = (k + 1 < BF) ? f_bonds[b * BF + k + 1] : 0.f;
    uint32_t h, l;
    split2(v0, v1, h, l);
    *(uint32_t*)&Ah[b * 160 + k] = h;
    *(uint32_t*)&Al[b * 160 + k] = l;
}

// pre[b][k] = amsg[b2a[b]][k] - msg[b2revb[b]][k]  -> Ahi/Alo [NBND x 320]
__global__ __launch_bounds__(256)
void presplit_kernel(const float* __restrict__ amsg, const float* __restrict__ msg,
                     const int* __restrict__ b2a, const int* __restrict__ b2revb,
                     unsigned short* __restrict__ Ah, unsigned short* __restrict__ Al)
{
    int idx = blockIdx.x * blockDim.x + threadIdx.x;   // quads
    if (idx >= NBND * 80) return;
    int b = idx / 80, q = idx - b * 80;
    uint2 hv = make_uint2(0u, 0u), lv = make_uint2(0u, 0u);
    if (q < 75) {
        float4 x = *(const float4*)&amsg[b2a[b] * HID + 4 * q];
        float4 y = *(const float4*)&msg[b2revb[b] * HID + 4 * q];
        split2(x.x - y.x, x.y - y.y, hv.x, lv.x);
        split2(x.z - y.z, x.w - y.w, hv.y, lv.y);
    }
    *(uint2*)&Ah[b * 320 + 4 * q] = hv;
    *(uint2*)&Al[b * 320 + 4 * q] = lv;
}

// concat(f_atoms[NA x 133], amsg[NA x 300]) -> Ahi/Alo [NA x 448]
__global__ __launch_bounds__(256)
void catsplit_kernel(const float* __restrict__ f_atoms, const float* __restrict__ amsg,
                     unsigned short* __restrict__ Ah, unsigned short* __restrict__ Al)
{
    int idx = blockIdx.x * blockDim.x + threadIdx.x;   // pairs
    if (idx >= NA * 224) return;
    int a = idx / 224, p = idx - a * 224;
    int k = 2 * p;
    float v0 = 0.f, v1 = 0.f;
    if (k < AF)                v0 = f_atoms[a * AF + k];
    else if (k < AF + HID)     v0 = amsg[a * HID + k - AF];
    if (k + 1 < AF)            v1 = f_atoms[a * AF + k + 1];
    else if (k + 1 < AF + HID) v1 = amsg[a * HID + k + 1 - AF];
    uint32_t h, l;
    split2(v0, v1, h, l);
    *(uint32_t*)&Ah[a * 448 + k] = h;
    *(uint32_t*)&Al[a * 448 + k] = l;
}

// ---------------------------------------------------------------------------
// Pure-async pipelined HMMA bf16x3 GEMM: C[M,300] = act( A @ W (+add) )
// Block 256x64, 8 warps (4m x 2n), warp 64x32 = 4x4 m16n8k16, BK=32,
// 2-stage cp.async. LDSM bytes/MMA: 128 (was 170 at 128x64).
// EPI 0: C=val, C2=relu(val); EPI 1: C=relu(val+add[row,col]); EPI 2: relu(val+add[col])
// ---------------------------------------------------------------------------
#define PITCH 40             // halves per smem row (80B, conflict-free ldmatrix)
#define ST_A  20480          // bytes per A stage (hi or lo): 256*40*2
#define ST_B  5120           // 64*40*2
#define OFF_AH 0             // 2 stages
#define OFF_AL 40960
#define OFF_BH 81920
#define OFF_BL 92160
#define SMEM_BYTES 102400

__device__ __forceinline__ void issue_chunk(uint32_t smb,
    const unsigned short* __restrict__ Ah, const unsigned short* __restrict__ Al,
    const unsigned short* __restrict__ Wh, const unsigned short* __restrict__ Wl,
    int row0, int col0, int Kp, int tid, int c)
{
    const int st = c & 1;
    const int k0 = c * 32;
#pragma unroll
    for (int i = 0; i < 4; i++) {
        int p = tid + i * 256;            // 0..1023
        int r = p >> 2, seg = p & 3;      // r 0..255, seg 0..3 (16B units)
        size_t gsrc = (size_t)(row0 + r) * Kp + k0 + seg * 8;
        uint32_t off = (uint32_t)(r * PITCH + seg * 8) * 2;
        CP_ASYNC16(smb + OFF_AH + st * ST_A + off, &Ah[gsrc]);
        CP_ASYNC16(smb + OFF_AL + st * ST_A + off, &Al[gsrc]);
    }
    {
        int r = tid >> 2, seg = tid & 3;  // r 0..63
        size_t gsrc = (size_t)(col0 + r) * Kp + k0 + seg * 8;
        uint32_t off = (uint32_t)(r * PITCH + seg * 8) * 2;
        CP_ASYNC16(smb + OFF_BH + st * ST_B + off, &Wh[gsrc]);
        CP_ASYNC16(smb + OFF_BL + st * ST_B + off, &Wl[gsrc]);
    }
    CP_COMMIT();
}

template<int EPI>
__global__ __launch_bounds__(256, 2)
void tgemm_kernel(const unsigned short* __restrict__ Ah, const unsigned short* __restrict__ Al,
                  const unsigned short* __restrict__ Whi, const unsigned short* __restrict__ Wlo,
                  const float* __restrict__ addsrc,
                  float* __restrict__ C, float* __restrict__ C2,
                  int M, int Kp)
{
    extern __shared__ char smem[];
    const uint32_t smb = (uint32_t)__cvta_generic_to_shared(smem);

    const int tid  = threadIdx.x;
    const int lane = tid & 31;
    const int w    = tid >> 5;
    const int wm   = w >> 1;             // 0..3 (64 rows each)
    const int wn   = w & 1;              // 0..1 (32 cols each)
    const int row0 = blockIdx.y * 256;
    const int col0 = blockIdx.x * 64;
    const int NC   = Kp >> 5;            // BK=32 chunks

    float acc[4][4][4];
#pragma unroll
    for (int mt = 0; mt < 4; mt++)
#pragma unroll
        for (int nt = 0; nt < 4; nt++)
#pragma unroll
            for (int e = 0; e < 4; e++) acc[mt][nt][e] = 0.f;

    issue_chunk(smb, Ah, Al, Whi, Wlo, row0, col0, Kp, tid, 0);
    issue_chunk(smb, Ah, Al, Whi, Wlo, row0, col0, Kp, tid, 1);

    const int lane15 = lane & 15;
    const int aCol   = (lane >> 4) << 3;
    const int bRow   = (lane & 7) + ((lane >> 4) << 3);
    const int bCol   = ((lane >> 3) & 1) << 3;

    for (int c = 0; c < NC; c++) {
        if (c + 1 < NC) { CP_WAIT1(); } else { CP_WAIT0(); }
        __syncthreads();

        const int st = c & 1;
        const uint32_t aBaseH = smb + OFF_AH + st * ST_A;
        const uint32_t bBaseH = smb + OFF_BH + st * ST_B;
#pragma unroll
        for (int ks = 0; ks < 2; ks++) {
            uint32_t ah[4][4], al[4][4], bh[4][2], bl[4][2];
#pragma unroll
            for (int mt = 0; mt < 4; mt++) {
                uint32_t addr = aBaseH + ((wm * 64 + mt * 16 + lane15) * PITCH + ks * 16 + aCol) * 2;
                LDSM_X4(ah[mt][0], ah[mt][1], ah[mt][2], ah[mt][3], addr);
                LDSM_X4(al[mt][0], al[mt][1], al[mt][2], al[mt][3], addr + (OFF_AL - OFF_AH));
            }
#pragma unroll
            for (int pp = 0; pp < 2; pp++) {
                uint32_t addr = bBaseH + ((wn * 32 + pp * 16 + bRow) * PITCH + ks * 16 + bCol) * 2;
                LDSM_X4(bh[2 * pp][0], bh[2 * pp][1], bh[2 * pp + 1][0], bh[2 * pp + 1][1], addr);
                LDSM_X4(bl[2 * pp][0], bl[2 * pp][1], bl[2 * pp + 1][0], bl[2 * pp + 1][1],
                        addr + (OFF_BL - OFF_BH));
            }
#pragma unroll
            for (int mt = 0; mt < 4; mt++)
#pragma unroll
                for (int nt = 0; nt < 4; nt++)
                    MMA16816(acc[mt][nt], ah[mt], bh[nt]);   // hi*hi
#pragma unroll
            for (int mt = 0; mt < 4; mt++)
#pragma unroll
                for (int nt = 0; nt < 4; nt++)
                    MMA16816(acc[mt][nt], ah[mt], bl[nt]);   // hi*lo
#pragma unroll
            for (int mt = 0; mt < 4; mt++)
#pragma unroll
                for (int nt = 0; nt < 4; nt++)
                    MMA16816(acc[mt][nt], al[mt], bh[nt]);   // lo*hi
        }
        __syncthreads();
        if (c + 2 < NC)
            issue_chunk(smb, Ah, Al, Whi, Wlo, row0, col0, Kp, tid, c + 2);
    }

    // ---- epilogue ----
#pragma unroll
    for (int mt = 0; mt < 4; mt++) {
#pragma unroll
        for (int nt = 0; nt < 4; nt++) {
            const int gc = col0 + wn * 32 + nt * 8 + (lane & 3) * 2;
            if (gc >= HID) continue;
#pragma unroll
            for (int h = 0; h < 2; h++) {
                const int gr = row0 + wm * 64 + mt * 16 + (lane >> 2) + h * 8;
                if (gr >= M) continue;
                float v0 = acc[mt][nt][2 * h];
                float v1 = acc[mt][nt][2 * h + 1];
                const int base = gr * HID + gc;
                if (EPI == 0) {
                    float2 raw; raw.x = v0; raw.y = v1;
                    *(float2*)&C[base] = raw;
                    float2 rl; rl.x = fmaxf(v0, 0.f); rl.y = fmaxf(v1, 0.f);
                    *(float2*)&C2[base] = rl;
                } else if (EPI == 1) {
                    float2 ad = *(const float2*)&addsrc[base];
                    float2 rl; rl.x = fmaxf(v0 + ad.x, 0.f); rl.y = fmaxf(v1 + ad.y, 0.f);
                    *(float2*)&C[base] = rl;
                } else {
                    float2 ad = *(const float2*)&addsrc[gc];
                    float2 rl; rl.x = fmaxf(v0 + ad.x, 0.f); rl.y = fmaxf(v1 + ad.y, 0.f);
                    *(float2*)&C[base] = rl;
                }
            }
        }
    }
}

// ---------------------------------------------------------------------------
#define H4 (HID / 4)
__global__ __launch_bounds__(256)
void gather_sum_kernel(const float* __restrict__ msg, const int* __restrict__ a2b,
                       float* __restrict__ amsg)
{
    int idx = blockIdx.x * blockDim.x + threadIdx.x;
    if (idx >= NA * H4) return;
    int a = idx / H4;
    int q = idx - a * H4;
    const int* nb = a2b + a * MAXNB;
    float4 s = make_float4(0.f, 0.f, 0.f, 0.f);
#pragma unroll
    for (int j = 0; j < MAXNB; j++) {
        float4 v = *(const float4*)&msg[nb[j] * HID + q * 4];
        s.x += v.x; s.y += v.y; s.z += v.z; s.w += v.w;
    }
    *(float4*)&amsg[a * HID + q * 4] = s;
}

__global__ __launch_bounds__(128)
void mol_mean_kernel(const float* __restrict__ hidden, const int* __restrict__ mol_ids,
                     float* __restrict__ out)
{
    int m = blockIdx.x;
    __shared__ int s_start, s_end;
    if (threadIdx.x == 0) {
        int lo = 0, hi = NA;
        while (lo < hi) { int mid = (lo + hi) >> 1; if (mol_ids[mid] < m) lo = mid + 1; else hi = mid; }
        s_start = lo;
        hi = NA;
        while (lo < hi) { int mid = (lo + hi) >> 1; if (mol_ids[mid] < m + 1) lo = mid + 1; else hi = mid; }
        s_end = lo;
    }
    __syncthreads();
    const int start = s_start, end = s_end;
    const float inv = 1.f / fmaxf((float)(end - start), 1.f);
    int q = threadIdx.x;
    if (q >= H4) return;
    float4 s = make_float4(0.f, 0.f, 0.f, 0.f);
    for (int a = start; a < end; a++) {
        float4 v = *(const float4*)&hidden[a * HID + q * 4];
        s.x += v.x; s.y += v.y; s.z += v.z; s.w += v.w;
    }
    s.x *= inv; s.y *= inv; s.z *= inv; s.w *= inv;
    *(float4*)&out[m * HID + q * 4] = s;
}

// ---------------------------------------------------------------------------
extern "C" void kernel_launch(void* const* d_in, const int* in_sizes, int n_in,
                              void* d_out, int out_size)
{
    const float* f_atoms = (const float*)d_in[0];
    const float* f_bonds = (const float*)d_in[1];
    const float* W_i     = (const float*)d_in[2];
    const float* W_h     = (const float*)d_in[3];
    const float* W_o     = (const float*)d_in[4];
    const float* b_o     = (const float*)d_in[5];
    const int*   a2b     = (const int*)d_in[6];
    const int*   b2a     = (const int*)d_in[7];
    const int*   b2revb  = (const int*)d_in[8];
    const int*   mol_ids = (const int*)d_in[9];
    float* out = (float*)d_out;

    float *inp, *bufA, *bufB, *amsg, *hid;
    cudaGetSymbolAddress((void**)&inp,  g_inp);
    cudaGetSymbolAddress((void**)&bufA, g_bufA);
    cudaGetSymbolAddress((void**)&bufB, g_bufB);
    cudaGetSymbolAddress((void**)&amsg, g_amsg);
    cudaGetSymbolAddress((void**)&hid,  g_hid);
    unsigned short *Ah, *Al;
    cudaGetSymbolAddress((void**)&Ah, g_Ahi);
    cudaGetSymbolAddress((void**)&Al, g_Alo);
    unsigned short *wi_h, *wi_l, *wh_h, *wh_l, *wo_h, *wo_l;
    cudaGetSymbolAddress((void**)&wi_h, g_Wi_hi);  cudaGetSymbolAddress((void**)&wi_l, g_Wi_lo);
    cudaGetSymbolAddress((void**)&wh_h, g_Wh_hi);  cudaGetSymbolAddress((void**)&wh_l, g_Wh_lo);
    cudaGetSymbolAddress((void**)&wo_h, g_Wo_hi);  cudaGetSymbolAddress((void**)&wo_l, g_Wo_lo);

    cudaFuncSetAttribute(tgemm_kernel<0>, cudaFuncAttributeMaxDynamicSharedMemorySize, SMEM_BYTES);
    cudaFuncSetAttribute(tgemm_kernel<1>, cudaFuncAttributeMaxDynamicSharedMemorySize, SMEM_BYTES);
    cudaFuncSetAttribute(tgemm_kernel<2>, cudaFuncAttributeMaxDynamicSharedMemorySize, SMEM_BYTES);

    // Weight splits (cheap)
    wsplit_kernel<<<(NPAD * 160 + 255) / 256, 256>>>(W_i, wi_h, wi_l, BF, 160);
    wsplit_kernel<<<(NPAD * 320 + 255) / 256, 256>>>(W_h, wh_h, wh_l, HID, 320);
    wsplit_kernel<<<(NPAD * 448 + 255) / 256, 256>>>(W_o, wo_h, wo_l, AF + HID, 448);

    const dim3 blk(256);
    const dim3 grid_b(5, (NBND + 255) / 256);   // (5, 782)
    const dim3 grid_a(5, (NA + 255) / 256);     // (5, 391)
    const int n_g = NA * H4;

    // 1) split f_bonds; inp = f_bonds @ W_i ; msg0 = relu(inp)
    bsplit_kernel<<<(NBND * 80 + 255) / 256, blk>>>(f_bonds, Ah, Al);
    tgemm_kernel<0><<<grid_b, blk, SMEM_BYTES>>>(Ah, Al, wi_h, wi_l, nullptr,
                                                 inp, bufA, NBND, 160);

    // 2) 3x message passing
    float* cur = bufA;
    float* nxt = bufB;
    for (int d = 0; d < 3; d++) {
        gather_sum_kernel<<<(n_g + 255) / 256, blk>>>(cur, a2b, amsg);
        presplit_kernel<<<(NBND * 80 + 255) / 256, blk>>>(amsg, cur, b2a, b2revb, Ah, Al);
        tgemm_kernel<1><<<grid_b, blk, SMEM_BYTES>>>(Ah, Al, wh_h, wh_l, inp,
                                                     nxt, nullptr, NBND, 320);
        float* t = cur; cur = nxt; nxt = t;
    }

    // 3) final neighbor sum + concat + readout
    gather_sum_kernel<<<(n_g + 255) / 256, blk>>>(cur, a2b, amsg);
    catsplit_kernel<<<(NA * 224 + 255) / 256, blk>>>(f_atoms, amsg, Ah, Al);
    tgemm_kernel<2><<<grid_a, blk, SMEM_BYTES>>>(Ah, Al, wo_h, wo_l, b_o,
                                                 hid, nullptr, NA, 448);

    // 4) per-molecule mean
    mol_mean_kernel<<<NM, 128>>>(hid, mol_ids, out);
}

// round 13
// speedup vs baseline: 1.2495x; 1.2495x over previous
#include <cuda_runtime.h>
#include <cuda_fp16.h>
#include <cstdint>

// Problem constants
#define NA     100000
#define NBND   200000
#define MAXNB  6
#define AF     133
#define BF     147
#define HID    300
#define NM     8192
#define NPAD   320
#define NBP    200064   // NBND rounded up to 128

// Scratch (device globals)
__device__ float g_inp [NBND * HID];
__device__ float g_bufA[NBND * HID];
__device__ float g_bufB[NBND * HID];
__device__ float g_amsg[NA   * HID];
__device__ float g_hid [NA   * HID];

// A operand: fp16 (hi only) [rows x Kp], reused across phases (x192 / x320 / x448)
__device__ __align__(16) unsigned short g_Ahi[NBP * 320];

// Pre-split transposed weights: Wt[n][k] fp16 hi/lo, zero-padded
__device__ __align__(16) unsigned short g_Wi_hi[NPAD * 192], g_Wi_lo[NPAD * 192];
__device__ __align__(16) unsigned short g_Wh_hi[NPAD * 320], g_Wh_lo[NPAD * 320];
__device__ __align__(16) unsigned short g_Wo_hi[NPAD * 448], g_Wo_lo[NPAD * 448];

#define MMA16816(d, a, b) \
    asm volatile("mma.sync.aligned.m16n8k16.row.col.f32.f16.f16.f32 " \
        "{%0,%1,%2,%3}, {%4,%5,%6,%7}, {%8,%9}, {%0,%1,%2,%3};" \
        : "+f"((d)[0]), "+f"((d)[1]), "+f"((d)[2]), "+f"((d)[3]) \
        : "r"((a)[0]), "r"((a)[1]), "r"((a)[2]), "r"((a)[3]), \
          "r"((b)[0]), "r"((b)[1]))

#define LDSM_X4(r0_, r1_, r2_, r3_, addr) \
    asm volatile("ldmatrix.sync.aligned.m8n8.x4.shared.b16 {%0,%1,%2,%3}, [%4];" \
        : "=r"(r0_), "=r"(r1_), "=r"(r2_), "=r"(r3_) : "r"(addr))

#define CP_ASYNC16(dst, src) \
    asm volatile("cp.async.cg.shared.global [%0], [%1], 16;" :: "r"(dst), "l"(src))
#define CP_COMMIT() asm volatile("cp.async.commit_group;")
#define CP_WAIT0()  asm volatile("cp.async.wait_group 0;")
#define CP_WAIT1()  asm volatile("cp.async.wait_group 1;")

__device__ __forceinline__ uint32_t packh2(float v0, float v1)
{
    __half h0 = __float2half(v0), h1 = __float2half(v1);
    return (uint32_t)__half_as_ushort(h0) | ((uint32_t)__half_as_ushort(h1) << 16);
}

// ---------------------------------------------------------------------------
// Split kernels
// ---------------------------------------------------------------------------
// Weights: fp16 hi/lo transposed, zero-padded
__global__ void wsplit_kernel(const float* __restrict__ W, unsigned short* __restrict__ hi,
                              unsigned short* __restrict__ lo, int K, int Kp)
{
    int idx = blockIdx.x * blockDim.x + threadIdx.x;
    if (idx >= NPAD * Kp) return;
    int n = idx / Kp, k = idx - n * Kp;
    float v = (n < HID && k < K) ? W[k * HID + n] : 0.f;
    __half h = __float2half(v);
    __half l = __float2half(v - __half2float(h));
    hi[idx] = __half_as_ushort(h);
    lo[idx] = __half_as_ushort(l);
}

// f_bonds [NBND x 147] -> Ah fp16 [NBND x 192]
__global__ __launch_bounds__(256)
void bsplit_kernel(const float* __restrict__ f_bonds, unsigned short* __restrict__ Ah)
{
    int idx = blockIdx.x * blockDim.x + threadIdx.x;   // pairs
    if (idx >= NBND * 96) return;
    int b = idx / 96, p = idx - b * 96;
    int k = 2 * p;
    float v0 = (k < BF)     ? f_bonds[b * BF + k]     : 0.f;
    float v1 = (k + 1 < BF) ? f_bonds[b * BF + k + 1] : 0.f;
    *(uint32_t*)&Ah[b * 192 + k] = packh2(v0, v1);
}

// pre[b][k] = amsg[b2a[b]][k] - msg[b2revb[b]][k]  -> Ah fp16 [NBND x 320]
__global__ __launch_bounds__(256)
void presplit_kernel(const float* __restrict__ amsg, const float* __restrict__ msg,
                     const int* __restrict__ b2a, const int* __restrict__ b2revb,
                     unsigned short* __restrict__ Ah)
{
    int idx = blockIdx.x * blockDim.x + threadIdx.x;   // quads
    if (idx >= NBND * 80) return;
    int b = idx / 80, q = idx - b * 80;
    uint2 hv = make_uint2(0u, 0u);
    if (q < 75) {
        float4 x = *(const float4*)&amsg[b2a[b] * HID + 4 * q];
        float4 y = *(const float4*)&msg[b2revb[b] * HID + 4 * q];
        hv.x = packh2(x.x - y.x, x.y - y.y);
        hv.y = packh2(x.z - y.z, x.w - y.w);
    }
    *(uint2*)&Ah[b * 320 + 4 * q] = hv;
}

// concat(f_atoms[NA x 133], amsg[NA x 300]) -> Ah fp16 [NA x 448]
__global__ __launch_bounds__(256)
void catsplit_kernel(const float* __restrict__ f_atoms, const float* __restrict__ amsg,
                     unsigned short* __restrict__ Ah)
{
    int idx = blockIdx.x * blockDim.x + threadIdx.x;   // pairs
    if (idx >= NA * 224) return;
    int a = idx / 224, p = idx - a * 224;
    int k = 2 * p;
    float v0 = 0.f, v1 = 0.f;
    if (k < AF)                v0 = f_atoms[a * AF + k];
    else if (k < AF + HID)     v0 = amsg[a * HID + k - AF];
    if (k + 1 < AF)            v1 = f_atoms[a * AF + k + 1];
    else if (k + 1 < AF + HID) v1 = amsg[a * HID + k + 1 - AF];
    *(uint32_t*)&Ah[a * 448 + k] = packh2(v0, v1);
}

// ---------------------------------------------------------------------------
// Pure-async pipelined HMMA fp16x2 GEMM: C[M,300] = act( A @ (Wh+Wl) (+add) )
// A = fp16 [M x Kp] gmem (hi only). BK=64 chunks, 2-stage cp.async,
// 64 MMA/warp per chunk. Block 128x64, 8 warps (4m x 2n), warp 32x32.
// EPI 0: C=val, C2=relu(val); EPI 1: C=relu(val+add[row,col]); EPI 2: relu(val+add[col])
// ---------------------------------------------------------------------------
#define PITCH 72             // halves per smem row (144B: 16B-aligned, conflict-free)
#define ST_A  18432          // bytes per A stage: 128*72*2
#define ST_B  9216           // 64*72*2
#define OFF_A  0             // 2 stages
#define OFF_BH 36864
#define OFF_BL 55296
#define SMEM_BYTES 73728

__device__ __forceinline__ void issue_chunk(uint32_t smb,
    const unsigned short* __restrict__ Ah,
    const unsigned short* __restrict__ Wh, const unsigned short* __restrict__ Wl,
    int row0, int col0, int Kp, int tid, int c)
{
    const int st = c & 1;
    const int k0 = c * 64;
#pragma unroll
    for (int i = 0; i < 4; i++) {
        int p = tid + i * 256;            // 0..1023
        int r = p >> 3, seg = p & 7;      // r 0..127, seg 0..7 (16B units)
        size_t gsrc = (size_t)(row0 + r) * Kp + k0 + seg * 8;
        uint32_t off = (uint32_t)(r * PITCH + seg * 8) * 2;
        CP_ASYNC16(smb + OFF_A + st * ST_A + off, &Ah[gsrc]);
    }
#pragma unroll
    for (int i = 0; i < 2; i++) {
        int p = tid + i * 256;            // 0..511
        int r = p >> 3, seg = p & 7;      // r 0..63
        size_t gsrc = (size_t)(col0 + r) * Kp + k0 + seg * 8;
        uint32_t off = (uint32_t)(r * PITCH + seg * 8) * 2;
        CP_ASYNC16(smb + OFF_BH + st * ST_B + off, &Wh[gsrc]);
        CP_ASYNC16(smb + OFF_BL + st * ST_B + off, &Wl[gsrc]);
    }
    CP_COMMIT();
}

template<int EPI>
__global__ __launch_bounds__(256, 2)
void tgemm_kernel(const unsigned short* __restrict__ Ah,
                  const unsigned short* __restrict__ Whi, const unsigned short* __restrict__ Wlo,
                  const float* __restrict__ addsrc,
                  float* __restrict__ C, float* __restrict__ C2,
                  int M, int Kp)
{
    extern __shared__ char smem[];
    const uint32_t smb = (uint32_t)__cvta_generic_to_shared(smem);

    const int tid  = threadIdx.x;
    const int lane = tid & 31;
    const int w    = tid >> 5;
    const int wm   = w >> 1;
    const int wn   = w & 1;
    const int row0 = blockIdx.y * 128;
    const int col0 = blockIdx.x * 64;
    const int NC   = Kp >> 6;            // BK=64 chunks

    float acc[2][4][4];
#pragma unroll
    for (int mt = 0; mt < 2; mt++)
#pragma unroll
        for (int nt = 0; nt < 4; nt++)
#pragma unroll
            for (int e = 0; e < 4; e++) acc[mt][nt][e] = 0.f;

    issue_chunk(smb, Ah, Whi, Wlo, row0, col0, Kp, tid, 0);
    issue_chunk(smb, Ah, Whi, Wlo, row0, col0, Kp, tid, 1);

    const int lane15 = lane & 15;
    const int aCol   = (lane >> 4) << 3;
    const int bRow   = (lane & 7) + ((lane >> 4) << 3);
    const int bCol   = ((lane >> 3) & 1) << 3;

    for (int c = 0; c < NC; c++) {
        if (c + 1 < NC) { CP_WAIT1(); } else { CP_WAIT0(); }
        __syncthreads();

        const int st = c & 1;
        const uint32_t aBase  = smb + OFF_A  + st * ST_A;
        const uint32_t bBaseH = smb + OFF_BH + st * ST_B;
#pragma unroll
        for (int ks = 0; ks < 4; ks++) {
            uint32_t ah[2][4], bh[4][2], bl[4][2];
#pragma unroll
            for (int mt = 0; mt < 2; mt++) {
                uint32_t addr = aBase + ((wm * 32 + mt * 16 + lane15) * PITCH + ks * 16 + aCol) * 2;
                LDSM_X4(ah[mt][0], ah[mt][1], ah[mt][2], ah[mt][3], addr);
            }
#pragma unroll
            for (int pp = 0; pp < 2; pp++) {
                uint32_t addr = bBaseH + ((wn * 32 + pp * 16 + bRow) * PITCH + ks * 16 + bCol) * 2;
                LDSM_X4(bh[2 * pp][0], bh[2 * pp][1], bh[2 * pp + 1][0], bh[2 * pp + 1][1], addr);
                LDSM_X4(bl[2 * pp][0], bl[2 * pp][1], bl[2 * pp + 1][0], bl[2 * pp + 1][1],
                        addr + (OFF_BL - OFF_BH));
            }
#pragma unroll
            for (int mt = 0; mt < 2; mt++)
#pragma unroll
                for (int nt = 0; nt < 4; nt++)
                    MMA16816(acc[mt][nt], ah[mt], bh[nt]);   // a*hiB
#pragma unroll
            for (int mt = 0; mt < 2; mt++)
#pragma unroll
                for (int nt = 0; nt < 4; nt++)
                    MMA16816(acc[mt][nt], ah[mt], bl[nt]);   // a*loB
        }
        __syncthreads();                 // stage st free for chunk c+2
        if (c + 2 < NC)
            issue_chunk(smb, Ah, Whi, Wlo, row0, col0, Kp, tid, c + 2);
    }

    // ---- epilogue ----
#pragma unroll
    for (int mt = 0; mt < 2; mt++) {
#pragma unroll
        for (int nt = 0; nt < 4; nt++) {
            const int gc = col0 + wn * 32 + nt * 8 + (lane & 3) * 2;
            if (gc >= HID) continue;
#pragma unroll
            for (int h = 0; h < 2; h++) {
                const int gr = row0 + wm * 32 + mt * 16 + (lane >> 2) + h * 8;
                if (gr >= M) continue;
                float v0 = acc[mt][nt][2 * h];
                float v1 = acc[mt][nt][2 * h + 1];
                const int base = gr * HID + gc;
                if (EPI == 0) {
                    float2 raw; raw.x = v0; raw.y = v1;
                    *(float2*)&C[base] = raw;
                    float2 rl; rl.x = fmaxf(v0, 0.f); rl.y = fmaxf(v1, 0.f);
                    *(float2*)&C2[base] = rl;
                } else if (EPI == 1) {
                    float2 ad = *(const float2*)&addsrc[base];
                    float2 rl; rl.x = fmaxf(v0 + ad.x, 0.f); rl.y = fmaxf(v1 + ad.y, 0.f);
                    *(float2*)&C[base] = rl;
                } else {
                    float2 ad = *(const float2*)&addsrc[gc];
                    float2 rl; rl.x = fmaxf(v0 + ad.x, 0.f); rl.y = fmaxf(v1 + ad.y, 0.f);
                    *(float2*)&C[base] = rl;
                }
            }
        }
    }
}

// ---------------------------------------------------------------------------
#define H4 (HID / 4)
__global__ __launch_bounds__(256)
void gather_sum_kernel(const float* __restrict__ msg, const int* __restrict__ a2b,
                       float* __restrict__ amsg)
{
    int idx = blockIdx.x * blockDim.x + threadIdx.x;
    if (idx >= NA * H4) return;
    int a = idx / H4;
    int q = idx - a * H4;
    const int* nb = a2b + a * MAXNB;
    float4 s = make_float4(0.f, 0.f, 0.f, 0.f);
#pragma unroll
    for (int j = 0; j < MAXNB; j++) {
        float4 v = *(const float4*)&msg[nb[j] * HID + q * 4];
        s.x += v.x; s.y += v.y; s.z += v.z; s.w += v.w;
    }
    *(float4*)&amsg[a * HID + q * 4] = s;
}

__global__ __launch_bounds__(128)
void mol_mean_kernel(const float* __restrict__ hidden, const int* __restrict__ mol_ids,
                     float* __restrict__ out)
{
    int m = blockIdx.x;
    __shared__ int s_start, s_end;
    if (threadIdx.x == 0) {
        int lo = 0, hi = NA;
        while (lo < hi) { int mid = (lo + hi) >> 1; if (mol_ids[mid] < m) lo = mid + 1; else hi = mid; }
        s_start = lo;
        hi = NA;
        while (lo < hi) { int mid = (lo + hi) >> 1; if (mol_ids[mid] < m + 1) lo = mid + 1; else hi = mid; }
        s_end = lo;
    }
    __syncthreads();
    const int start = s_start, end = s_end;
    const float inv = 1.f / fmaxf((float)(end - start), 1.f);
    int q = threadIdx.x;
    if (q >= H4) return;
    float4 s = make_float4(0.f, 0.f, 0.f, 0.f);
    for (int a = start; a < end; a++) {
        float4 v = *(const float4*)&hidden[a * HID + q * 4];
        s.x += v.x; s.y += v.y; s.z += v.z; s.w += v.w;
    }
    s.x *= inv; s.y *= inv; s.z *= inv; s.w *= inv;
    *(float4*)&out[m * HID + q * 4] = s;
}

// ---------------------------------------------------------------------------
extern "C" void kernel_launch(void* const* d_in, const int* in_sizes, int n_in,
                              void* d_out, int out_size)
{
    const float* f_atoms = (const float*)d_in[0];
    const float* f_bonds = (const float*)d_in[1];
    const float* W_i     = (const float*)d_in[2];
    const float* W_h     = (const float*)d_in[3];
    const float* W_o     = (const float*)d_in[4];
    const float* b_o     = (const float*)d_in[5];
    const int*   a2b     = (const int*)d_in[6];
    const int*   b2a     = (const int*)d_in[7];
    const int*   b2revb  = (const int*)d_in[8];
    const int*   mol_ids = (const int*)d_in[9];
    float* out = (float*)d_out;

    float *inp, *bufA, *bufB, *amsg, *hid;
    cudaGetSymbolAddress((void**)&inp,  g_inp);
    cudaGetSymbolAddress((void**)&bufA, g_bufA);
    cudaGetSymbolAddress((void**)&bufB, g_bufB);
    cudaGetSymbolAddress((void**)&amsg, g_amsg);
    cudaGetSymbolAddress((void**)&hid,  g_hid);
    unsigned short *Ah;
    cudaGetSymbolAddress((void**)&Ah, g_Ahi);
    unsigned short *wi_h, *wi_l, *wh_h, *wh_l, *wo_h, *wo_l;
    cudaGetSymbolAddress((void**)&wi_h, g_Wi_hi);  cudaGetSymbolAddress((void**)&wi_l, g_Wi_lo);
    cudaGetSymbolAddress((void**)&wh_h, g_Wh_hi);  cudaGetSymbolAddress((void**)&wh_l, g_Wh_lo);
    cudaGetSymbolAddress((void**)&wo_h, g_Wo_hi);  cudaGetSymbolAddress((void**)&wo_l, g_Wo_lo);

    cudaFuncSetAttribute(tgemm_kernel<0>, cudaFuncAttributeMaxDynamicSharedMemorySize, SMEM_BYTES);
    cudaFuncSetAttribute(tgemm_kernel<1>, cudaFuncAttributeMaxDynamicSharedMemorySize, SMEM_BYTES);
    cudaFuncSetAttribute(tgemm_kernel<2>, cudaFuncAttributeMaxDynamicSharedMemorySize, SMEM_BYTES);

    // Weight splits (cheap)
    wsplit_kernel<<<(NPAD * 192 + 255) / 256, 256>>>(W_i, wi_h, wi_l, BF, 192);
    wsplit_kernel<<<(NPAD * 320 + 255) / 256, 256>>>(W_h, wh_h, wh_l, HID, 320);
    wsplit_kernel<<<(NPAD * 448 + 255) / 256, 256>>>(W_o, wo_h, wo_l, AF + HID, 448);

    const dim3 blk(256);
    const dim3 grid_b(5, (NBND + 127) / 128);   // (5, 1563)
    const dim3 grid_a(5, (NA + 127) / 128);     // (5, 782)
    const int n_g = NA * H4;

    // 1) split f_bonds; inp = f_bonds @ W_i ; msg0 = relu(inp)
    bsplit_kernel<<<(NBND * 96 + 255) / 256, blk>>>(f_bonds, Ah);
    tgemm_kernel<0><<<grid_b, blk, SMEM_BYTES>>>(Ah, wi_h, wi_l, nullptr,
                                                 inp, bufA, NBND, 192);

    // 2) 3x message passing
    float* cur = bufA;
    float* nxt = bufB;
    for (int d = 0; d < 3; d++) {
        gather_sum_kernel<<<(n_g + 255) / 256, blk>>>(cur, a2b, amsg);
        presplit_kernel<<<(NBND * 80 + 255) / 256, blk>>>(amsg, cur, b2a, b2revb, Ah);
        tgemm_kernel<1><<<grid_b, blk, SMEM_BYTES>>>(Ah, wh_h, wh_l, inp,
                                                     nxt, nullptr, NBND, 320);
        float* t = cur; cur = nxt; nxt = t;
    }

    // 3) final neighbor sum + concat + readout
    gather_sum_kernel<<<(n_g + 255) / 256, blk>>>(cur, a2b, amsg);
    catsplit_kernel<<<(NA * 224 + 255) / 256, blk>>>(f_atoms, amsg, Ah);
    tgemm_kernel<2><<<grid_a, blk, SMEM_BYTES>>>(Ah, wo_h, wo_l, b_o,
                                                 hid, nullptr, NA, 448);

    // 4) per-molecule mean
    mol_mean_kernel<<<NM, 128>>>(hid, mol_ids, out);
}

// round 15
// speedup vs baseline: 1.4362x; 1.1494x over previous
#include <cuda_runtime.h>
#include <cuda_fp16.h>
#include <cstdint>

// Problem constants
#define NA     100000
#define NBND   200000
#define MAXNB  6
#define AF     133
#define BF     147
#define HID    300
#define NM     8192
#define NPAD   320
#define NBP    200064   // NBND rounded up to 128
#define MSGP   304      // message row pitch in halves (608B, 16B-aligned)

// Scratch (device globals; zero-initialized => pad columns stay 0)
__device__ float g_inp [NBND * HID];
__device__ float g_hid [NA   * HID];
__device__ __align__(16) __half g_bufA[NBND * MSGP];
__device__ __align__(16) __half g_bufB[NBND * MSGP];
__device__ __align__(16) __half g_amsg[NA   * MSGP];

// A operand: fp16 (hi only) [rows x Kp], reused across phases (x192 / x320 / x448)
__device__ __align__(16) unsigned short g_Ahi[NBP * 320];

// Pre-split transposed weights: Wt[n][k] fp16 hi/lo, zero-padded
__device__ __align__(16) unsigned short g_Wi_hi[NPAD * 192], g_Wi_lo[NPAD * 192];
__device__ __align__(16) unsigned short g_Wh_hi[NPAD * 320], g_Wh_lo[NPAD * 320];
__device__ __align__(16) unsigned short g_Wo_hi[NPAD * 448], g_Wo_lo[NPAD * 448];

#define MMA16816(d, a, b) \
    asm volatile("mma.sync.aligned.m16n8k16.row.col.f32.f16.f16.f32 " \
        "{%0,%1,%2,%3}, {%4,%5,%6,%7}, {%8,%9}, {%0,%1,%2,%3};" \
        : "+f"((d)[0]), "+f"((d)[1]), "+f"((d)[2]), "+f"((d)[3]) \
        : "r"((a)[0]), "r"((a)[1]), "r"((a)[2]), "r"((a)[3]), \
          "r"((b)[0]), "r"((b)[1]))

#define LDSM_X4(r0_, r1_, r2_, r3_, addr) \
    asm volatile("ldmatrix.sync.aligned.m8n8.x4.shared.b16 {%0,%1,%2,%3}, [%4];" \
        : "=r"(r0_), "=r"(r1_), "=r"(r2_), "=r"(r3_) : "r"(addr))

#define CP_ASYNC16(dst, src) \
    asm volatile("cp.async.cg.shared.global [%0], [%1], 16;" :: "r"(dst), "l"(src))
#define CP_COMMIT() asm volatile("cp.async.commit_group;")
#define CP_WAIT0()  asm volatile("cp.async.wait_group 0;")
#define CP_WAIT1()  asm volatile("cp.async.wait_group 1;")

__device__ __forceinline__ uint32_t packh2(float v0, float v1)
{
    __half h0 = __float2half(v0), h1 = __float2half(v1);
    return (uint32_t)__half_as_ushort(h0) | ((uint32_t)__half_as_ushort(h1) << 16);
}

// ---------------------------------------------------------------------------
// Split kernels
// ---------------------------------------------------------------------------
__global__ void wsplit_kernel(const float* __restrict__ W, unsigned short* __restrict__ hi,
                              unsigned short* __restrict__ lo, int K, int Kp)
{
    int idx = blockIdx.x * blockDim.x + threadIdx.x;
    if (idx >= NPAD * Kp) return;
    int n = idx / Kp, k = idx - n * Kp;
    float v = (n < HID && k < K) ? W[k * HID + n] : 0.f;
    __half h = __float2half(v);
    __half l = __float2half(v - __half2float(h));
    hi[idx] = __half_as_ushort(h);
    lo[idx] = __half_as_ushort(l);
}

// f_bonds [NBND x 147] -> Ah fp16 [NBND x 192]
__global__ __launch_bounds__(256)
void bsplit_kernel(const float* __restrict__ f_bonds, unsigned short* __restrict__ Ah)
{
    int idx = blockIdx.x * blockDim.x + threadIdx.x;   // pairs
    if (idx >= NBND * 96) return;
    int b = idx / 96, p = idx - b * 96;
    int k = 2 * p;
    float v0 = (k < BF)     ? f_bonds[b * BF + k]     : 0.f;
    float v1 = (k + 1 < BF) ? f_bonds[b * BF + k + 1] : 0.f;
    *(uint32_t*)&Ah[b * 192 + k] = packh2(v0, v1);
}

// a_message[a] = sum_j msg[a2b[a,j]]  (fp16 msg, f32 accumulate, fp16 out)
__global__ __launch_bounds__(256)
void gather_sum_kernel(const __half* __restrict__ msg, const int* __restrict__ a2b,
                       __half* __restrict__ amsg)
{
    int idx = blockIdx.x * blockDim.x + threadIdx.x;   // 8 halves per thread
    if (idx >= NA * 38) return;
    int a = idx / 38, seg = idx - a * 38;
    const int* nb = a2b + a * MAXNB;
    float2 s0 = {0.f, 0.f}, s1 = {0.f, 0.f}, s2 = {0.f, 0.f}, s3 = {0.f, 0.f};
#pragma unroll
    for (int j = 0; j < MAXNB; j++) {
        uint4 v = *(const uint4*)&msg[nb[j] * MSGP + seg * 8];
        float2 f0 = __half22float2(*(__half2*)&v.x);
        float2 f1 = __half22float2(*(__half2*)&v.y);
        float2 f2 = __half22float2(*(__half2*)&v.z);
        float2 f3 = __half22float2(*(__half2*)&v.w);
        s0.x += f0.x; s0.y += f0.y; s1.x += f1.x; s1.y += f1.y;
        s2.x += f2.x; s2.y += f2.y; s3.x += f3.x; s3.y += f3.y;
    }
    uint4 o;
    o.x = packh2(s0.x, s0.y); o.y = packh2(s1.x, s1.y);
    o.z = packh2(s2.x, s2.y); o.w = packh2(s3.x, s3.y);
    *(uint4*)&amsg[a * MSGP + seg * 8] = o;
}

// pre[b] = amsg[b2a[b]] - msg[b2revb[b]]  -> Ah fp16 [NBND x 320]
__global__ __launch_bounds__(256)
void presplit_kernel(const __half* __restrict__ amsg, const __half* __restrict__ msg,
                     const int* __restrict__ b2a, const int* __restrict__ b2revb,
                     unsigned short* __restrict__ Ah)
{
    int idx = blockIdx.x * blockDim.x + threadIdx.x;   // 8 halves per thread
    if (idx >= NBND * 40) return;
    int b = idx / 40, q = idx - b * 40;
    uint4 o = {0u, 0u, 0u, 0u};
    if (q < 38) {     // pad halves 300..303 are 0-0=0; k 304..319 -> zeros
        uint4 x4 = *(const uint4*)&amsg[b2a[b] * MSGP + q * 8];
        uint4 y4 = *(const uint4*)&msg[b2revb[b] * MSGP + q * 8];
        float2 a0 = __half22float2(*(__half2*)&x4.x), b0 = __half22float2(*(__half2*)&y4.x);
        float2 a1 = __half22float2(*(__half2*)&x4.y), b1 = __half22float2(*(__half2*)&y4.y);
        float2 a2 = __half22float2(*(__half2*)&x4.z), b2 = __half22float2(*(__half2*)&y4.z);
        float2 a3 = __half22float2(*(__half2*)&x4.w), b3 = __half22float2(*(__half2*)&y4.w);
        o.x = packh2(a0.x - b0.x, a0.y - b0.y);
        o.y = packh2(a1.x - b1.x, a1.y - b1.y);
        o.z = packh2(a2.x - b2.x, a2.y - b2.y);
        o.w = packh2(a3.x - b3.x, a3.y - b3.y);
    }
    *(uint4*)&Ah[b * 320 + q * 8] = o;
}

// concat(f_atoms[NA x 133], amsg fp16[NA x 300]) -> Ah fp16 [NA x 448]
__global__ __launch_bounds__(256)
void catsplit_kernel(const float* __restrict__ f_atoms, const __half* __restrict__ amsg,
                     unsigned short* __restrict__ Ah)
{
    int idx = blockIdx.x * blockDim.x + threadIdx.x;   // pairs
    if (idx >= NA * 224) return;
    int a = idx / 224, p = idx - a * 224;
    int k = 2 * p;
    float v0 = 0.f, v1 = 0.f;
    if (k < AF)                v0 = f_atoms[a * AF + k];
    else if (k < AF + HID)     v0 = __half2float(amsg[a * MSGP + k - AF]);
    if (k + 1 < AF)            v1 = f_atoms[a * AF + k + 1];
    else if (k + 1 < AF + HID) v1 = __half2float(amsg[a * MSGP + k + 1 - AF]);
    *(uint32_t*)&Ah[a * 448 + k] = packh2(v0, v1);
}

// ---------------------------------------------------------------------------
// Pure-async pipelined HMMA fp16 GEMM: out = act( A @ (Wh+Wl) (+add) )
// A = fp16 [M x Kp] gmem. BK=64 chunks, 2-stage cp.async, block 128x64,
// 8 warps (4m x 2n), warp 32x32. 64 MMA/warp per chunk.
// EPI 0: Cf=val (f32), Ch=relu(val) (fp16 msg)
// EPI 1: Ch=relu(val + addsrc[row,col]) (fp16 msg)
// EPI 2: Cf=relu(val + addsrc[col]) (f32 hid)
// ---------------------------------------------------------------------------
#define PITCH 72
#define ST_A  18432
#define ST_B  9216
#define OFF_A  0
#define OFF_BH 36864
#define OFF_BL 55296
#define SMEM_BYTES 73728

__device__ __forceinline__ void issue_chunk(uint32_t smb,
    const unsigned short* __restrict__ Ah,
    const unsigned short* __restrict__ Wh, const unsigned short* __restrict__ Wl,
    int row0, int col0, int Kp, int tid, int c)
{
    const int st = c & 1;
    const int k0 = c * 64;
#pragma unroll
    for (int i = 0; i < 4; i++) {
        int p = tid + i * 256;
        int r = p >> 3, seg = p & 7;
        size_t gsrc = (size_t)(row0 + r) * Kp + k0 + seg * 8;
        uint32_t off = (uint32_t)(r * PITCH + seg * 8) * 2;
        CP_ASYNC16(smb + OFF_A + st * ST_A + off, &Ah[gsrc]);
    }
#pragma unroll
    for (int i = 0; i < 2; i++) {
        int p = tid + i * 256;
        int r = p >> 3, seg = p & 7;
        size_t gsrc = (size_t)(col0 + r) * Kp + k0 + seg * 8;
        uint32_t off = (uint32_t)(r * PITCH + seg * 8) * 2;
        CP_ASYNC16(smb + OFF_BH + st * ST_B + off, &Wh[gsrc]);
        CP_ASYNC16(smb + OFF_BL + st * ST_B + off, &Wl[gsrc]);
    }
    CP_COMMIT();
}

template<int EPI>
__global__ __launch_bounds__(256, 2)
void tgemm_kernel(const unsigned short* __restrict__ Ah,
                  const unsigned short* __restrict__ Whi, const unsigned short* __restrict__ Wlo,
                  const float* __restrict__ addsrc,
                  float* __restrict__ Cf, __half* __restrict__ Ch,
                  int M, int Kp)
{
    extern __shared__ char smem[];
    const uint32_t smb = (uint32_t)__cvta_generic_to_shared(smem);

    const int tid  = threadIdx.x;
    const int lane = tid & 31;
    const int w    = tid >> 5;
    const int wm   = w >> 1;
    const int wn   = w & 1;
    const int row0 = blockIdx.y * 128;
    const int col0 = blockIdx.x * 64;
    const int NC   = Kp >> 6;

    float acc[2][4][4];
#pragma unroll
    for (int mt = 0; mt < 2; mt++)
#pragma unroll
        for (int nt = 0; nt < 4; nt++)
#pragma unroll
            for (int e = 0; e < 4; e++) acc[mt][nt][e] = 0.f;

    issue_chunk(smb, Ah, Whi, Wlo, row0, col0, Kp, tid, 0);
    issue_chunk(smb, Ah, Whi, Wlo, row0, col0, Kp, tid, 1);

    const int lane15 = lane & 15;
    const int aCol   = (lane >> 4) << 3;
    const int bRow   = (lane & 7) + ((lane >> 4) << 3);
    const int bCol   = ((lane >> 3) & 1) << 3;

    for (int c = 0; c < NC; c++) {
        if (c + 1 < NC) { CP_WAIT1(); } else { CP_WAIT0(); }
        __syncthreads();

        const int st = c & 1;
        const uint32_t aBase  = smb + OFF_A  + st * ST_A;
        const uint32_t bBaseH = smb + OFF_BH + st * ST_B;
#pragma unroll
        for (int ks = 0; ks < 4; ks++) {
            uint32_t ah[2][4], bh[4][2], bl[4][2];
#pragma unroll
            for (int mt = 0; mt < 2; mt++) {
                uint32_t addr = aBase + ((wm * 32 + mt * 16 + lane15) * PITCH + ks * 16 + aCol) * 2;
                LDSM_X4(ah[mt][0], ah[mt][1], ah[mt][2], ah[mt][3], addr);
            }
#pragma unroll
            for (int pp = 0; pp < 2; pp++) {
                uint32_t addr = bBaseH + ((wn * 32 + pp * 16 + bRow) * PITCH + ks * 16 + bCol) * 2;
                LDSM_X4(bh[2 * pp][0], bh[2 * pp][1], bh[2 * pp + 1][0], bh[2 * pp + 1][1], addr);
                LDSM_X4(bl[2 * pp][0], bl[2 * pp][1], bl[2 * pp + 1][0], bl[2 * pp + 1][1],
                        addr + (OFF_BL - OFF_BH));
            }
#pragma unroll
            for (int mt = 0; mt < 2; mt++)
#pragma unroll
                for (int nt = 0; nt < 4; nt++)
                    MMA16816(acc[mt][nt], ah[mt], bh[nt]);   // a*hiB
#pragma unroll
            for (int mt = 0; mt < 2; mt++)
#pragma unroll
                for (int nt = 0; nt < 4; nt++)
                    MMA16816(acc[mt][nt], ah[mt], bl[nt]);   // a*loB
        }
        __syncthreads();
        if (c + 2 < NC)
            issue_chunk(smb, Ah, Whi, Wlo, row0, col0, Kp, tid, c + 2);
    }

    // ---- epilogue ----
#pragma unroll
    for (int mt = 0; mt < 2; mt++) {
#pragma unroll
        for (int nt = 0; nt < 4; nt++) {
            const int gc = col0 + wn * 32 + nt * 8 + (lane & 3) * 2;
            if (gc >= HID) continue;
#pragma unroll
            for (int h = 0; h < 2; h++) {
                const int gr = row0 + wm * 32 + mt * 16 + (lane >> 2) + h * 8;
                if (gr >= M) continue;
                float v0 = acc[mt][nt][2 * h];
                float v1 = acc[mt][nt][2 * h + 1];
                if (EPI == 0) {
                    float2 raw; raw.x = v0; raw.y = v1;
                    *(float2*)&Cf[gr * HID + gc] = raw;
                    *(uint32_t*)&Ch[gr * MSGP + gc] = packh2(fmaxf(v0, 0.f), fmaxf(v1, 0.f));
                } else if (EPI == 1) {
                    float2 ad = *(const float2*)&addsrc[gr * HID + gc];
                    *(uint32_t*)&Ch[gr * MSGP + gc] =
                        packh2(fmaxf(v0 + ad.x, 0.f), fmaxf(v1 + ad.y, 0.f));
                } else {
                    float2 ad = *(const float2*)&addsrc[gc];
                    float2 rl; rl.x = fmaxf(v0 + ad.x, 0.f); rl.y = fmaxf(v1 + ad.y, 0.f);
                    *(float2*)&Cf[gr * HID + gc] = rl;
                }
            }
        }
    }
}

// ---------------------------------------------------------------------------
#define H4 (HID / 4)
__global__ __launch_bounds__(128)
void mol_mean_kernel(const float* __restrict__ hidden, const int* __restrict__ mol_ids,
                     float* __restrict__ out)
{
    int m = blockIdx.x;
    __shared__ int s_start, s_end;
    if (threadIdx.x == 0) {
        int lo = 0, hi = NA;
        while (lo < hi) { int mid = (lo + hi) >> 1; if (mol_ids[mid] < m) lo = mid + 1; else hi = mid; }
        s_start = lo;
        hi = NA;
        while (lo < hi) { int mid = (lo + hi) >> 1; if (mol_ids[mid] < m + 1) lo = mid + 1; else hi = mid; }
        s_end = lo;
    }
    __syncthreads();
    const int start = s_start, end = s_end;
    const float inv = 1.f / fmaxf((float)(end - start), 1.f);
    int q = threadIdx.x;
    if (q >= H4) return;
    float4 s = make_float4(0.f, 0.f, 0.f, 0.f);
    for (int a = start; a < end; a++) {
        float4 v = *(const float4*)&hidden[a * HID + q * 4];
        s.x += v.x; s.y += v.y; s.z += v.z; s.w += v.w;
    }
    s.x *= inv; s.y *= inv; s.z *= inv; s.w *= inv;
    *(float4*)&out[m * HID + q * 4] = s;
}

// ---------------------------------------------------------------------------
extern "C" void kernel_launch(void* const* d_in, const int* in_sizes, int n_in,
                              void* d_out, int out_size)
{
    const float* f_atoms = (const float*)d_in[0];
    const float* f_bonds = (const float*)d_in[1];
    const float* W_i     = (const float*)d_in[2];
    const float* W_h     = (const float*)d_in[3];
    const float* W_o     = (const float*)d_in[4];
    const float* b_o     = (const float*)d_in[5];
    const int*   a2b     = (const int*)d_in[6];
    const int*   b2a     = (const int*)d_in[7];
    const int*   b2revb  = (const int*)d_in[8];
    const int*   mol_ids = (const int*)d_in[9];
    float* out = (float*)d_out;

    float *inp, *hid;
    __half *bufA, *bufB, *amsg;
    cudaGetSymbolAddress((void**)&inp,  g_inp);
    cudaGetSymbolAddress((void**)&hid,  g_hid);
    cudaGetSymbolAddress((void**)&bufA, g_bufA);
    cudaGetSymbolAddress((void**)&bufB, g_bufB);
    cudaGetSymbolAddress((void**)&amsg, g_amsg);
    unsigned short *Ah;
    cudaGetSymbolAddress((void**)&Ah, g_Ahi);
    unsigned short *wi_h, *wi_l, *wh_h, *wh_l, *wo_h, *wo_l;
    cudaGetSymbolAddress((void**)&wi_h, g_Wi_hi);  cudaGetSymbolAddress((void**)&wi_l, g_Wi_lo);
    cudaGetSymbolAddress((void**)&wh_h, g_Wh_hi);  cudaGetSymbolAddress((void**)&wh_l, g_Wh_lo);
    cudaGetSymbolAddress((void**)&wo_h, g_Wo_hi);  cudaGetSymbolAddress((void**)&wo_l, g_Wo_lo);

    cudaFuncSetAttribute(tgemm_kernel<0>, cudaFuncAttributeMaxDynamicSharedMemorySize, SMEM_BYTES);
    cudaFuncSetAttribute(tgemm_kernel<1>, cudaFuncAttributeMaxDynamicSharedMemorySize, SMEM_BYTES);
    cudaFuncSetAttribute(tgemm_kernel<2>, cudaFuncAttributeMaxDynamicSharedMemorySize, SMEM_BYTES);

    // Weight splits (cheap)
    wsplit_kernel<<<(NPAD * 192 + 255) / 256, 256>>>(W_i, wi_h, wi_l, BF, 192);
    wsplit_kernel<<<(NPAD * 320 + 255) / 256, 256>>>(W_h, wh_h, wh_l, HID, 320);
    wsplit_kernel<<<(NPAD * 448 + 255) / 256, 256>>>(W_o, wo_h, wo_l, AF + HID, 448);

    const dim3 blk(256);
    const dim3 grid_b(5, (NBND + 127) / 128);   // (5, 1563)
    const dim3 grid_a(5, (NA + 127) / 128);     // (5, 782)

    // 1) split f_bonds; inp = f_bonds @ W_i ; msg0 = relu(inp) (fp16)
    bsplit_kernel<<<(NBND * 96 + 255) / 256, blk>>>(f_bonds, Ah);
    tgemm_kernel<0><<<grid_b, blk, SMEM_BYTES>>>(Ah, wi_h, wi_l, nullptr,
                                                 inp, bufA, NBND, 192);

    // 2) 3x message passing (fp16 messages)
    __half* cur = bufA;
    __half* nxt = bufB;
    for (int d = 0; d < 3; d++) {
        gather_sum_kernel<<<(NA * 38 + 255) / 256, blk>>>(cur, a2b, amsg);
        presplit_kernel<<<(NBND * 40 + 255) / 256, blk>>>(amsg, cur, b2a, b2revb, Ah);
        tgemm_kernel<1><<<grid_b, blk, SMEM_BYTES>>>(Ah, wh_h, wh_l, inp,
                                                     nullptr, nxt, NBND, 320);
        __half* t = cur; cur = nxt; nxt = t;
    }

    // 3) final neighbor sum + concat + readout
    gather_sum_kernel<<<(NA * 38 + 255) / 256, blk>>>(cur, a2b, amsg);
    catsplit_kernel<<<(NA * 224 + 255) / 256, blk>>>(f_atoms, amsg, Ah);
    tgemm_kernel<2><<<grid_a, blk, SMEM_BYTES>>>(Ah, wo_h, wo_l, b_o,
                                                 hid, nullptr, NA, 448);

    // 4) per-molecule mean
    mol_mean_kernel<<<NM, 128>>>(hid, mol_ids, out);
}

// round 17
// speedup vs baseline: 1.7827x; 1.2413x over previous
#include <cuda_runtime.h>
#include <cuda_fp16.h>
#include <cstdint>

// Problem constants
#define NA     100000
#define NBND   200000
#define MAXNB  6
#define AF     133
#define BF     147
#define HID    300
#define NM     8192
#define NPAD   320
#define NBP    200064   // NBND rounded up to 128
#define MSGP   304      // message row pitch in halves (608B, 16B-aligned)

// Scratch (device globals; zero-initialized => pad columns stay 0)
__device__ float g_hid [NA   * HID];
__device__ __align__(16) __half g_inp [NBND * MSGP];
__device__ __align__(16) __half g_bufA[NBND * MSGP];
__device__ __align__(16) __half g_bufB[NBND * MSGP];
__device__ __align__(16) __half g_amsg[NA   * MSGP];

// A operand: fp16 [rows x Kp], reused across phases (x192 / x320 / x448)
__device__ __align__(16) unsigned short g_Ahi[NBP * 320];

// Transposed fp16 weights: Wt[n][k], zero-padded
__device__ __align__(16) unsigned short g_Wi[NPAD * 192];
__device__ __align__(16) unsigned short g_Wh[NPAD * 320];
__device__ __align__(16) unsigned short g_Wo[NPAD * 448];

#define MMA16816(d, a, b) \
    asm volatile("mma.sync.aligned.m16n8k16.row.col.f32.f16.f16.f32 " \
        "{%0,%1,%2,%3}, {%4,%5,%6,%7}, {%8,%9}, {%0,%1,%2,%3};" \
        : "+f"((d)[0]), "+f"((d)[1]), "+f"((d)[2]), "+f"((d)[3]) \
        : "r"((a)[0]), "r"((a)[1]), "r"((a)[2]), "r"((a)[3]), \
          "r"((b)[0]), "r"((b)[1]))

#define LDSM_X4(r0_, r1_, r2_, r3_, addr) \
    asm volatile("ldmatrix.sync.aligned.m8n8.x4.shared.b16 {%0,%1,%2,%3}, [%4];" \
        : "=r"(r0_), "=r"(r1_), "=r"(r2_), "=r"(r3_) : "r"(addr))

#define CP_ASYNC16(dst, src) \
    asm volatile("cp.async.cg.shared.global [%0], [%1], 16;" :: "r"(dst), "l"(src))
#define CP_COMMIT() asm volatile("cp.async.commit_group;")
#define CP_WAIT0()  asm volatile("cp.async.wait_group 0;")
#define CP_WAIT1()  asm volatile("cp.async.wait_group 1;")

__device__ __forceinline__ uint32_t packh2(float v0, float v1)
{
    __half h0 = __float2half(v0), h1 = __float2half(v1);
    return (uint32_t)__half_as_ushort(h0) | ((uint32_t)__half_as_ushort(h1) << 16);
}

// ---------------------------------------------------------------------------
// Split kernels
// ---------------------------------------------------------------------------
__global__ void wsplit_kernel(const float* __restrict__ W, unsigned short* __restrict__ hi,
                              int K, int Kp)
{
    int idx = blockIdx.x * blockDim.x + threadIdx.x;
    if (idx >= NPAD * Kp) return;
    int n = idx / Kp, k = idx - n * Kp;
    float v = (n < HID && k < K) ? W[k * HID + n] : 0.f;
    hi[idx] = __half_as_ushort(__float2half(v));
}

// f_bonds [NBND x 147] -> Ah fp16 [NBND x 192]
__global__ __launch_bounds__(256)
void bsplit_kernel(const float* __restrict__ f_bonds, unsigned short* __restrict__ Ah)
{
    int idx = blockIdx.x * blockDim.x + threadIdx.x;   // pairs
    if (idx >= NBND * 96) return;
    int b = idx / 96, p = idx - b * 96;
    int k = 2 * p;
    float v0 = (k < BF)     ? f_bonds[b * BF + k]     : 0.f;
    float v1 = (k + 1 < BF) ? f_bonds[b * BF + k + 1] : 0.f;
    *(uint32_t*)&Ah[b * 192 + k] = packh2(v0, v1);
}

// a_message[a] = sum_j msg[a2b[a,j]]  (fp16 msg, f32 accumulate, fp16 out)
__global__ __launch_bounds__(256)
void gather_sum_kernel(const __half* __restrict__ msg, const int* __restrict__ a2b,
                       __half* __restrict__ amsg)
{
    int idx = blockIdx.x * blockDim.x + threadIdx.x;   // 8 halves per thread
    if (idx >= NA * 38) return;
    int a = idx / 38, seg = idx - a * 38;
    const int* nb = a2b + a * MAXNB;
    float2 s0 = {0.f, 0.f}, s1 = {0.f, 0.f}, s2 = {0.f, 0.f}, s3 = {0.f, 0.f};
#pragma unroll
    for (int j = 0; j < MAXNB; j++) {
        uint4 v = *(const uint4*)&msg[nb[j] * MSGP + seg * 8];
        float2 f0 = __half22float2(*(__half2*)&v.x);
        float2 f1 = __half22float2(*(__half2*)&v.y);
        float2 f2 = __half22float2(*(__half2*)&v.z);
        float2 f3 = __half22float2(*(__half2*)&v.w);
        s0.x += f0.x; s0.y += f0.y; s1.x += f1.x; s1.y += f1.y;
        s2.x += f2.x; s2.y += f2.y; s3.x += f3.x; s3.y += f3.y;
    }
    uint4 o;
    o.x = packh2(s0.x, s0.y); o.y = packh2(s1.x, s1.y);
    o.z = packh2(s2.x, s2.y); o.w = packh2(s3.x, s3.y);
    *(uint4*)&amsg[a * MSGP + seg * 8] = o;
}

// pre[b] = amsg[b2a[b]] - msg[b2revb[b]]  -> Ah fp16 [NBND x 320]
__global__ __launch_bounds__(256)
void presplit_kernel(const __half* __restrict__ amsg, const __half* __restrict__ msg,
                     const int* __restrict__ b2a, const int* __restrict__ b2revb,
                     unsigned short* __restrict__ Ah)
{
    int idx = blockIdx.x * blockDim.x + threadIdx.x;   // 8 halves per thread
    if (idx >= NBND * 40) return;
    int b = idx / 40, q = idx - b * 40;
    uint4 o = {0u, 0u, 0u, 0u};
    if (q < 38) {
        uint4 x4 = *(const uint4*)&amsg[b2a[b] * MSGP + q * 8];
        uint4 y4 = *(const uint4*)&msg[b2revb[b] * MSGP + q * 8];
        float2 a0 = __half22float2(*(__half2*)&x4.x), b0 = __half22float2(*(__half2*)&y4.x);
        float2 a1 = __half22float2(*(__half2*)&x4.y), b1 = __half22float2(*(__half2*)&y4.y);
        float2 a2 = __half22float2(*(__half2*)&x4.z), b2 = __half22float2(*(__half2*)&y4.z);
        float2 a3 = __half22float2(*(__half2*)&x4.w), b3 = __half22float2(*(__half2*)&y4.w);
        o.x = packh2(a0.x - b0.x, a0.y - b0.y);
        o.y = packh2(a1.x - b1.x, a1.y - b1.y);
        o.z = packh2(a2.x - b2.x, a2.y - b2.y);
        o.w = packh2(a3.x - b3.x, a3.y - b3.y);
    }
    *(uint4*)&Ah[b * 320 + q * 8] = o;
}

// concat(f_atoms[NA x 133], amsg fp16[NA x 300]) -> Ah fp16 [NA x 448]
__global__ __launch_bounds__(256)
void catsplit_kernel(const float* __restrict__ f_atoms, const __half* __restrict__ amsg,
                     unsigned short* __restrict__ Ah)
{
    int idx = blockIdx.x * blockDim.x + threadIdx.x;   // pairs
    if (idx >= NA * 224) return;
    int a = idx / 224, p = idx - a * 224;
    int k = 2 * p;
    float v0 = 0.f, v1 = 0.f;
    if (k < AF)                v0 = f_atoms[a * AF + k];
    else if (k < AF + HID)     v0 = __half2float(amsg[a * MSGP + k - AF]);
    if (k + 1 < AF)            v1 = f_atoms[a * AF + k + 1];
    else if (k + 1 < AF + HID) v1 = __half2float(amsg[a * MSGP + k + 1 - AF]);
    *(uint32_t*)&Ah[a * 448 + k] = packh2(v0, v1);
}

// ---------------------------------------------------------------------------
// Pure-async pipelined HMMA fp16 GEMM: out = act( A @ W (+add) )
// A, W fp16 gmem. BK=64 chunks, 2-stage cp.async, block 128x64,
// 8 warps (4m x 2n), warp 32x32. 32 MMA/warp per chunk.
// EPI 0: Ch2=val (fp16 inp), Ch=relu(val) (fp16 msg)
// EPI 1: Ch=relu(val + addh[row,col]) (fp16 msg)
// EPI 2: Cf=relu(val + addf[col]) (f32 hid)
// ---------------------------------------------------------------------------
#define PITCH 72
#define ST_A  18432
#define ST_B  9216
#define OFF_A  0
#define OFF_B  36864
#define SMEM_BYTES 55296

__device__ __forceinline__ void issue_chunk(uint32_t smb,
    const unsigned short* __restrict__ Ah, const unsigned short* __restrict__ Wh,
    int row0, int col0, int Kp, int tid, int c)
{
    const int st = c & 1;
    const int k0 = c * 64;
#pragma unroll
    for (int i = 0; i < 4; i++) {
        int p = tid + i * 256;
        int r = p >> 3, seg = p & 7;
        size_t gsrc = (size_t)(row0 + r) * Kp + k0 + seg * 8;
        uint32_t off = (uint32_t)(r * PITCH + seg * 8) * 2;
        CP_ASYNC16(smb + OFF_A + st * ST_A + off, &Ah[gsrc]);
    }
#pragma unroll
    for (int i = 0; i < 2; i++) {
        int p = tid + i * 256;
        int r = p >> 3, seg = p & 7;
        size_t gsrc = (size_t)(col0 + r) * Kp + k0 + seg * 8;
        uint32_t off = (uint32_t)(r * PITCH + seg * 8) * 2;
        CP_ASYNC16(smb + OFF_B + st * ST_B + off, &Wh[gsrc]);
    }
    CP_COMMIT();
}

template<int EPI>
__global__ __launch_bounds__(256, 2)
void tgemm_kernel(const unsigned short* __restrict__ Ah,
                  const unsigned short* __restrict__ Whi,
                  const float* __restrict__ addf, const __half* __restrict__ addh,
                  float* __restrict__ Cf, __half* __restrict__ Ch, __half* __restrict__ Ch2,
                  int M, int Kp)
{
    extern __shared__ char smem[];
    const uint32_t smb = (uint32_t)__cvta_generic_to_shared(smem);

    const int tid  = threadIdx.x;
    const int lane = tid & 31;
    const int w    = tid >> 5;
    const int wm   = w >> 1;
    const int wn   = w & 1;
    const int row0 = blockIdx.y * 128;
    const int col0 = blockIdx.x * 64;
    const int NC   = Kp >> 6;

    float acc[2][4][4];
#pragma unroll
    for (int mt = 0; mt < 2; mt++)
#pragma unroll
        for (int nt = 0; nt < 4; nt++)
#pragma unroll
            for (int e = 0; e < 4; e++) acc[mt][nt][e] = 0.f;

    issue_chunk(smb, Ah, Whi, row0, col0, Kp, tid, 0);
    issue_chunk(smb, Ah, Whi, row0, col0, Kp, tid, 1);

    const int lane15 = lane & 15;
    const int aCol   = (lane >> 4) << 3;
    const int bRow   = (lane & 7) + ((lane >> 4) << 3);
    const int bCol   = ((lane >> 3) & 1) << 3;

    for (int c = 0; c < NC; c++) {
        if (c + 1 < NC) { CP_WAIT1(); } else { CP_WAIT0(); }
        __syncthreads();

        const int st = c & 1;
        const uint32_t aBase = smb + OFF_A + st * ST_A;
        const uint32_t bBase = smb + OFF_B + st * ST_B;
#pragma unroll
        for (int ks = 0; ks < 4; ks++) {
            uint32_t ah[2][4], bh[4][2];
#pragma unroll
            for (int mt = 0; mt < 2; mt++) {
                uint32_t addr = aBase + ((wm * 32 + mt * 16 + lane15) * PITCH + ks * 16 + aCol) * 2;
                LDSM_X4(ah[mt][0], ah[mt][1], ah[mt][2], ah[mt][3], addr);
            }
#pragma unroll
            for (int pp = 0; pp < 2; pp++) {
                uint32_t addr = bBase + ((wn * 32 + pp * 16 + bRow) * PITCH + ks * 16 + bCol) * 2;
                LDSM_X4(bh[2 * pp][0], bh[2 * pp][1], bh[2 * pp + 1][0], bh[2 * pp + 1][1], addr);
            }
#pragma unroll
            for (int mt = 0; mt < 2; mt++)
#pragma unroll
                for (int nt = 0; nt < 4; nt++)
                    MMA16816(acc[mt][nt], ah[mt], bh[nt]);
        }
        __syncthreads();
        if (c + 2 < NC)
            issue_chunk(smb, Ah, Whi, row0, col0, Kp, tid, c + 2);
    }

    // ---- epilogue ----
#pragma unroll
    for (int mt = 0; mt < 2; mt++) {
#pragma unroll
        for (int nt = 0; nt < 4; nt++) {
            const int gc = col0 + wn * 32 + nt * 8 + (lane & 3) * 2;
            if (gc >= HID) continue;
#pragma unroll
            for (int h = 0; h < 2; h++) {
                const int gr = row0 + wm * 32 + mt * 16 + (lane >> 2) + h * 8;
                if (gr >= M) continue;
                float v0 = acc[mt][nt][2 * h];
                float v1 = acc[mt][nt][2 * h + 1];
                if (EPI == 0) {
                    *(uint32_t*)&Ch2[gr * MSGP + gc] = packh2(v0, v1);
                    *(uint32_t*)&Ch[gr * MSGP + gc] = packh2(fmaxf(v0, 0.f), fmaxf(v1, 0.f));
                } else if (EPI == 1) {
                    uint32_t aw = *(const uint32_t*)&addh[gr * MSGP + gc];
                    float2 ad = __half22float2(*(__half2*)&aw);
                    *(uint32_t*)&Ch[gr * MSGP + gc] =
                        packh2(fmaxf(v0 + ad.x, 0.f), fmaxf(v1 + ad.y, 0.f));
                } else {
                    float2 ad = *(const float2*)&addf[gc];
                    float2 rl; rl.x = fmaxf(v0 + ad.x, 0.f); rl.y = fmaxf(v1 + ad.y, 0.f);
                    *(float2*)&Cf[gr * HID + gc] = rl;
                }
            }
        }
    }
}

// ---------------------------------------------------------------------------
#define H4 (HID / 4)
__global__ __launch_bounds__(128)
void mol_mean_kernel(const float* __restrict__ hidden, const int* __restrict__ mol_ids,
                     float* __restrict__ out)
{
    int m = blockIdx.x;
    __shared__ int s_start, s_end;
    if (threadIdx.x == 0) {
        int lo = 0, hi = NA;
        while (lo < hi) { int mid = (lo + hi) >> 1; if (mol_ids[mid] < m) lo = mid + 1; else hi = mid; }
        s_start = lo;
        hi = NA;
        while (lo < hi) { int mid = (lo + hi) >> 1; if (mol_ids[mid] < m + 1) lo = mid + 1; else hi = mid; }
        s_end = lo;
    }
    __syncthreads();
    const int start = s_start, end = s_end;
    const float inv = 1.f / fmaxf((float)(end - start), 1.f);
    int q = threadIdx.x;
    if (q >= H4) return;
    float4 s = make_float4(0.f, 0.f, 0.f, 0.f);
    for (int a = start; a < end; a++) {
        float4 v = *(const float4*)&hidden[a * HID + q * 4];
        s.x += v.x; s.y += v.y; s.z += v.z; s.w += v.w;
    }
    s.x *= inv; s.y *= inv; s.z *= inv; s.w *= inv;
    *(float4*)&out[m * HID + q * 4] = s;
}

// ---------------------------------------------------------------------------
extern "C" void kernel_launch(void* const* d_in, const int* in_sizes, int n_in,
                              void* d_out, int out_size)
{
    const float* f_atoms = (const float*)d_in[0];
    const float* f_bonds = (const float*)d_in[1];
    const float* W_i     = (const float*)d_in[2];
    const float* W_h     = (const float*)d_in[3];
    const float* W_o     = (const float*)d_in[4];
    const float* b_o     = (const float*)d_in[5];
    const int*   a2b     = (const int*)d_in[6];
    const int*   b2a     = (const int*)d_in[7];
    const int*   b2revb  = (const int*)d_in[8];
    const int*   mol_ids = (const int*)d_in[9];
    float* out = (float*)d_out;

    float *hid;
    __half *inp, *bufA, *bufB, *amsg;
    cudaGetSymbolAddress((void**)&hid,  g_hid);
    cudaGetSymbolAddress((void**)&inp,  g_inp);
    cudaGetSymbolAddress((void**)&bufA, g_bufA);
    cudaGetSymbolAddress((void**)&bufB, g_bufB);
    cudaGetSymbolAddress((void**)&amsg, g_amsg);
    unsigned short *Ah, *wi, *wh, *wo;
    cudaGetSymbolAddress((void**)&Ah, g_Ahi);
    cudaGetSymbolAddress((void**)&wi, g_Wi);
    cudaGetSymbolAddress((void**)&wh, g_Wh);
    cudaGetSymbolAddress((void**)&wo, g_Wo);

    cudaFuncSetAttribute(tgemm_kernel<0>, cudaFuncAttributeMaxDynamicSharedMemorySize, SMEM_BYTES);
    cudaFuncSetAttribute(tgemm_kernel<1>, cudaFuncAttributeMaxDynamicSharedMemorySize, SMEM_BYTES);
    cudaFuncSetAttribute(tgemm_kernel<2>, cudaFuncAttributeMaxDynamicSharedMemorySize, SMEM_BYTES);

    // Weight transpose+quantize (cheap)
    wsplit_kernel<<<(NPAD * 192 + 255) / 256, 256>>>(W_i, wi, BF, 192);
    wsplit_kernel<<<(NPAD * 320 + 255) / 256, 256>>>(W_h, wh, HID, 320);
    wsplit_kernel<<<(NPAD * 448 + 255) / 256, 256>>>(W_o, wo, AF + HID, 448);

    const dim3 blk(256);
    const dim3 grid_b(5, (NBND + 127) / 128);   // (5, 1563)
    const dim3 grid_a(5, (NA + 127) / 128);     // (5, 782)

    // 1) split f_bonds; inp = f_bonds @ W_i (fp16) ; msg0 = relu(inp) (fp16)
    bsplit_kernel<<<(NBND * 96 + 255) / 256, blk>>>(f_bonds, Ah);
    tgemm_kernel<0><<<grid_b, blk, SMEM_BYTES>>>(Ah, wi, nullptr, nullptr,
                                                 nullptr, bufA, inp, NBND, 192);

    // 2) 3x message passing (fp16 messages)
    __half* cur = bufA;
    __half* nxt = bufB;
    for (int d = 0; d < 3; d++) {
        gather_sum_kernel<<<(NA * 38 + 255) / 256, blk>>>(cur, a2b, amsg);
        presplit_kernel<<<(NBND * 40 + 255) / 256, blk>>>(amsg, cur, b2a, b2revb, Ah);
        tgemm_kernel<1><<<grid_b, blk, SMEM_BYTES>>>(Ah, wh, nullptr, inp,
                                                     nullptr, nxt, nullptr, NBND, 320);
        __half* t = cur; cur = nxt; nxt = t;
    }

    // 3) final neighbor sum + concat + readout
    gather_sum_kernel<<<(NA * 38 + 255) / 256, blk>>>(cur, a2b, amsg);
    catsplit_kernel<<<(NA * 224 + 255) / 256, blk>>>(f_atoms, amsg, Ah);
    tgemm_kernel<2><<<grid_a, blk, SMEM_BYTES>>>(Ah, wo, b_o, nullptr,
                                                 hid, nullptr, nullptr, NA, 448);

    // 4) per-molecule mean
    mol_mean_kernel<<<NM, 128>>>(hid, mol_ids, out);
}